// round 5
// baseline (speedup 1.0000x reference)
#include <cuda_runtime.h>

#define HH 1024
#define WW 1024
#define NPIX (HH * WW)

// Persistent device-global scratch (no cudaMalloc allowed).
__device__ float4 g_P[NPIX];    // row-normalized 4-neighbor weights; all-zero at seeds
__device__ float2 g_buf[NPIX];  // ping-pong partner of d_out

__global__ __launch_bounds__(256)
void rw_setup_kernel(const float* __restrict__ img,
                     const int* __restrict__ seeds,
                     float2* __restrict__ x0)
{
    int j = blockIdx.x * 32 + threadIdx.x;
    int i = blockIdx.y * blockDim.y + threadIdx.y;
    int idx = i * WW + j;

    float c  = img[idx];
    bool  cb = (c > 0.1f);

    const int di[4] = {-1, 1, 0, 0};
    const int dj[4] = { 0, 0,-1, 1};

    float w[4];
    float rowsum = 0.0f;
#pragma unroll
    for (int d = 0; d < 4; d++) {
        int ni = i + di[d], nj = j + dj[d];
        bool valid = (ni >= 0) && (ni < HH) && (nj >= 0) && (nj < WW);
        int nidx = (valid ? ni : i) * WW + (valid ? nj : j);
        float nb = img[nidx];
        float same = ((nb > 0.1f) != cb) ? 1.0f : 0.0f;
        float diff = c - nb + same;
        float wt = valid ? expf(-1.0f - fabsf(diff)) : 0.0f;
        w[d] = wt;
        rowsum += wt;
    }
    float inv = 1.0f / rowsum;

    int s = seeds[idx];
    // Seed rows are absorbing: all-zero weights -> self coefficient = 1 exactly.
    float4 p = s ? make_float4(0.f, 0.f, 0.f, 0.f)
                 : make_float4(w[0] * inv, w[1] * inv, w[2] * inv, w[3] * inv);
    g_P[idx] = p;

    float2 x;
    x.x = (s == 1) ? 1.0f : 0.0f;
    x.y = (s == 2) ? 1.0f : 0.0f;
    x0[idx] = x;
}

// Two Jacobi steps per launch. x staged in smem (radius-2 halo); P read
// directly from L2-resident global (no smem copy). 7 blocks/SM -> single wave.
#define TX 32
#define TY 32
#define XW (TX + 4)   // 36
#define YW (TX + 2)   // 34

__global__ __launch_bounds__(256, 7)
void rw_step2_kernel(const float2* __restrict__ xin,
                     float2* __restrict__ xout)
{
    __shared__ float2 sx[XW][XW];  // 36x36 x, radius 2   (10.4 KB)
    __shared__ float2 sy[YW][YW];  // 34x34 step-1 output ( 9.2 KB)

    const int tid = threadIdx.x;           // 0..255
    const int bx  = blockIdx.x * TX;
    const int by  = blockIdx.y * TY;

    // ---- load x with radius-2 halo (zero-padded outside image) ----
#pragma unroll 1
    for (int e = tid; e < XW * XW; e += 256) {
        int r = e / XW, c = e % XW;
        int gy = by - 2 + r, gx = bx - 2 + c;
        float2 v = make_float2(0.f, 0.f);
        if ((unsigned)gy < HH && (unsigned)gx < WW) v = xin[gy * WW + gx];
        sx[r][c] = v;
    }
    __syncthreads();

    // ---- step 1: compute y on tile + radius-1 halo (34x34); P from global ----
#pragma unroll 1
    for (int e = tid; e < YW * YW; e += 256) {
        int r = e / YW, c = e % YW;          // y-space; x-space offset +1
        int gy = by - 1 + r, gx = bx - 1 + c;
        float4 p = make_float4(0.f, 0.f, 0.f, 0.f);
        if ((unsigned)gy < HH && (unsigned)gx < WW) p = g_P[gy * WW + gx];
        float2 up = sx[r    ][c + 1];
        float2 dn = sx[r + 2][c + 1];
        float2 lf = sx[r + 1][c    ];
        float2 rt = sx[r + 1][c + 2];
        float2 ct = sx[r + 1][c + 1];
        float self = 1.0f - (p.x + p.y + p.z + p.w);
        float2 o;
        o.x = p.x * up.x + p.y * dn.x + p.z * lf.x + p.w * rt.x + self * ct.x;
        o.y = p.x * up.y + p.y * dn.y + p.z * lf.y + p.w * rt.y + self * ct.y;
        sy[r][c] = o;
    }
    __syncthreads();

    // ---- step 2: compute z on the 32x32 tile (always in-bounds), write global ----
#pragma unroll 1
    for (int e = tid; e < TX * TY; e += 256) {
        int r = e / TX, c = e % TX;          // tile space; y-space offset +1
        float4 p = g_P[(by + r) * WW + (bx + c)];
        float2 up = sy[r    ][c + 1];
        float2 dn = sy[r + 2][c + 1];
        float2 lf = sy[r + 1][c    ];
        float2 rt = sy[r + 1][c + 2];
        float2 ct = sy[r + 1][c + 1];
        float self = 1.0f - (p.x + p.y + p.z + p.w);
        float2 o;
        o.x = p.x * up.x + p.y * dn.x + p.z * lf.x + p.w * rt.x + self * ct.x;
        o.y = p.x * up.y + p.y * dn.y + p.z * lf.y + p.w * rt.y + self * ct.y;
        xout[(by + r) * WW + (bx + c)] = o;
    }
}

extern "C" void kernel_launch(void* const* d_in, const int* in_sizes, int n_in,
                              void* d_out, int out_size)
{
    const float* img   = (const float*)d_in[0];
    const int*   seeds = (const int*)d_in[1];
    float2*      A     = (float2*)d_out;   // ping buffer; final write lands here

    float2* B = nullptr;
    cudaGetSymbolAddress((void**)&B, g_buf);

    {
        dim3 blk(32, 8);
        dim3 grd(WW / 32, HH / 8);
        rw_setup_kernel<<<grd, blk>>>(img, seeds, A);
    }

    // 100 Jacobi steps = 50 double-step kernels.
    // t even: A->B ; t odd: B->A.  t=49 (odd) writes A = d_out.
    dim3 blk(256);
    dim3 grd(WW / TX, HH / TY);
    for (int t = 0; t < 50; t++) {
        const float2* xin  = (t & 1) ? B : A;
        float2*       xout = (t & 1) ? A : B;
        rw_step2_kernel<<<grd, blk>>>(xin, xout);
    }
}

// round 6
// speedup vs baseline: 1.0293x; 1.0293x over previous
#include <cuda_runtime.h>

#define HH 1024
#define WW 1024
#define NPIX (HH * WW)

// Persistent device-global scratch (no cudaMalloc allowed).
__device__ float4 g_P[NPIX];    // row-normalized 4-neighbor weights; all-zero at seeds
__device__ float2 g_buf[NPIX];  // ping-pong partner of d_out

__global__ __launch_bounds__(256)
void rw_setup_kernel(const float* __restrict__ img,
                     const int* __restrict__ seeds,
                     float2* __restrict__ x0)
{
    int j = blockIdx.x * 32 + threadIdx.x;
    int i = blockIdx.y * blockDim.y + threadIdx.y;
    int idx = i * WW + j;

    float c  = img[idx];
    bool  cb = (c > 0.1f);

    const int di[4] = {-1, 1, 0, 0};
    const int dj[4] = { 0, 0,-1, 1};

    float w[4];
    float rowsum = 0.0f;
#pragma unroll
    for (int d = 0; d < 4; d++) {
        int ni = i + di[d], nj = j + dj[d];
        bool valid = (ni >= 0) && (ni < HH) && (nj >= 0) && (nj < WW);
        int nidx = (valid ? ni : i) * WW + (valid ? nj : j);
        float nb = img[nidx];
        float same = ((nb > 0.1f) != cb) ? 1.0f : 0.0f;
        float diff = c - nb + same;
        float wt = valid ? expf(-1.0f - fabsf(diff)) : 0.0f;
        w[d] = wt;
        rowsum += wt;
    }
    float inv = 1.0f / rowsum;

    int s = seeds[idx];
    // Seed rows are absorbing: all-zero weights -> self coefficient = 1 exactly.
    float4 p = s ? make_float4(0.f, 0.f, 0.f, 0.f)
                 : make_float4(w[0] * inv, w[1] * inv, w[2] * inv, w[3] * inv);
    g_P[idx] = p;

    float2 x;
    x.x = (s == 1) ? 1.0f : 0.0f;
    x.y = (s == 2) ? 1.0f : 0.0f;
    x0[idx] = x;
}

// ---------------------------------------------------------------------------
// Four Jacobi steps per launch. x/y ping-pong in smem; P read from L2-resident
// global each sub-step (L2 has huge headroom). 7 blocks/SM -> single wave.
//   bufA: 40x40, global origin (by-4, bx-4)
//   bufB: 38x38, global origin (by-3, bx-3)
// Phase s computes y_{s+1} on a region of radius 3-s around the 32x32 tile.
// ---------------------------------------------------------------------------
#define TX 32
#define TY 32
#define AW 40
#define BW 38

// One Jacobi sub-step over a DxD region (smem -> smem).
//  D    : output region side
//  IW   : input buffer stride
//  CI   : center offset of output-region origin inside input buffer
//  OW   : output buffer stride
//  OOFF : offset of output-region origin inside output buffer
//  PR   : radius of output region (P coords are by-PR+r, bx-PR+c)
//  GUARD: whether P coords can be out of image
template<int D, int IW, int CI, int OW, int OOFF, int PR, bool GUARD>
__device__ __forceinline__
void rw_phase(int tid, int by, int bx,
              const float2* __restrict__ sin_, float2* __restrict__ sout)
{
#pragma unroll 1
    for (int e = tid; e < D * D; e += 256) {
        int r = e / D, c = e % D;
        int gy = by - PR + r, gx = bx - PR + c;
        float4 p;
        if (GUARD) {
            p = make_float4(0.f, 0.f, 0.f, 0.f);
            if ((unsigned)gy < HH && (unsigned)gx < WW) p = g_P[gy * WW + gx];
        } else {
            p = g_P[gy * WW + gx];
        }
        const float2* ctp = sin_ + (r + CI) * IW + (c + CI);
        float2 up = ctp[-IW];
        float2 dn = ctp[ IW];
        float2 lf = ctp[ -1];
        float2 rt = ctp[  1];
        float2 ct = ctp[  0];
        float self = 1.0f - (p.x + p.y + p.z + p.w);
        float2 o;
        o.x = p.x * up.x + p.y * dn.x + p.z * lf.x + p.w * rt.x + self * ct.x;
        o.y = p.x * up.y + p.y * dn.y + p.z * lf.y + p.w * rt.y + self * ct.y;
        sout[(r + OOFF) * OW + (c + OOFF)] = o;
    }
}

__global__ __launch_bounds__(256, 7)
void rw_step4_kernel(const float2* __restrict__ xin,
                     float2* __restrict__ xout)
{
    __shared__ float2 sA[AW * AW];  // 12.8 KB
    __shared__ float2 sB[BW * BW];  // 11.5 KB

    const int tid = threadIdx.x;
    const int bx  = blockIdx.x * TX;
    const int by  = blockIdx.y * TY;

    // ---- load x with radius-4 halo into sA (zero-padded outside image) ----
#pragma unroll 1
    for (int e = tid; e < AW * AW; e += 256) {
        int r = e / AW, c = e % AW;
        int gy = by - 4 + r, gx = bx - 4 + c;
        float2 v = make_float2(0.f, 0.f);
        if ((unsigned)gy < HH && (unsigned)gx < WW) v = xin[gy * WW + gx];
        sA[e] = v;
    }
    __syncthreads();

    // phase 0: A(r4) -> B(r3)
    rw_phase<38, AW, 1, BW, 0, 3, true>(tid, by, bx, sA, sB);
    __syncthreads();
    // phase 1: B(r3) -> A(r2), stored at offset 2 in A
    rw_phase<36, BW, 1, AW, 2, 2, true>(tid, by, bx, sB, sA);
    __syncthreads();
    // phase 2: A(r2) -> B(r1), stored at offset 2 in B
    rw_phase<34, AW, 3, BW, 2, 1, true>(tid, by, bx, sA, sB);
    __syncthreads();

    // phase 3: B(r1) -> global 32x32 tile (always in-bounds)
#pragma unroll 1
    for (int e = tid; e < TX * TY; e += 256) {
        int r = e / TX, c = e % TX;
        float4 p = g_P[(by + r) * WW + (bx + c)];
        const float2* ctp = sB + (r + 3) * BW + (c + 3);
        float2 up = ctp[-BW];
        float2 dn = ctp[ BW];
        float2 lf = ctp[ -1];
        float2 rt = ctp[  1];
        float2 ct = ctp[  0];
        float self = 1.0f - (p.x + p.y + p.z + p.w);
        float2 o;
        o.x = p.x * up.x + p.y * dn.x + p.z * lf.x + p.w * rt.x + self * ct.x;
        o.y = p.x * up.y + p.y * dn.y + p.z * lf.y + p.w * rt.y + self * ct.y;
        xout[(by + r) * WW + (bx + c)] = o;
    }
}

extern "C" void kernel_launch(void* const* d_in, const int* in_sizes, int n_in,
                              void* d_out, int out_size)
{
    const float* img   = (const float*)d_in[0];
    const int*   seeds = (const int*)d_in[1];
    float2*      A     = (float2*)d_out;

    float2* B = nullptr;
    cudaGetSymbolAddress((void**)&B, g_buf);

    {
        dim3 blk(32, 8);
        dim3 grd(WW / 32, HH / 8);
        // x0 written into B; 25 quad-step kernels alternate B->A->B...,
        // t=24 (even) writes A = d_out.
        rw_setup_kernel<<<grd, blk>>>(img, seeds, B);
    }

    dim3 blk(256);
    dim3 grd(WW / TX, HH / TY);
    for (int t = 0; t < 25; t++) {
        const float2* xin  = (t & 1) ? A : B;
        float2*       xout = (t & 1) ? B : A;
        rw_step4_kernel<<<grd, blk>>>(xin, xout);
    }
}